// round 2
// baseline (speedup 1.0000x reference)
#include <cuda_runtime.h>
#include <math.h>

#define NN 16384
#define EE 131072
#define BB 16
#define HH 2
#define MAXD 512
#define MAXHD 1024
#define OUTC 896

// ---------------- scratch (device globals; no allocation) ----------------
__device__ float g_x[(size_t)NN * MAXHD];   // raw GAT output per layer
__device__ float g_y[(size_t)NN * MAXHD];   // normalized output (next layer input)
__device__ float g_h[(size_t)NN * MAXHD];   // h = x @ W
__device__ float g_r[(size_t)NN * MAXHD];   // res = x @ rW
__device__ float g_el[NN * HH];
__device__ float g_er[NN * HH];
__device__ int   g_indptr[NN + 1];
__device__ int   g_cnt[NN];
__device__ int   g_cur[NN];
__device__ int   g_esrc[EE];
__device__ float g_s1[MAXD];
__device__ float g_s2[MAXD];
__device__ float g_scale[MAXD];
__device__ float g_bias[MAXD];
__device__ float g_parts[BB * OUTC];
__device__ int   g_counts[BB];

__device__ __forceinline__ float lrelu(float v, float s) { return v > 0.f ? v : s * v; }

// ---------------- misc zero / histogram / CSR ----------------
__global__ void k_zero_front() {
    int i = blockIdx.x * blockDim.x + threadIdx.x;
    if (i < BB * OUTC) g_parts[i] = 0.f;
    if (i < BB) g_counts[i] = 0;
    if (i < NN) g_cnt[i] = 0;
}

__global__ void k_counts(const int* __restrict__ gid) {
    int i = blockIdx.x * blockDim.x + threadIdx.x;
    if (i < NN) atomicAdd(&g_counts[gid[i]], 1);
}

__global__ void k_hist(const int* __restrict__ dst) {
    int i = blockIdx.x * blockDim.x + threadIdx.x;
    if (i < EE) atomicAdd(&g_cnt[dst[i]], 1);
}

__global__ void k_scan() {  // one block, 1024 threads; NN = 1024*16
    __shared__ int sums[1024];
    int tid = threadIdx.x;
    int base = tid * 16;
    int loc[16];
    int s = 0;
#pragma unroll
    for (int i = 0; i < 16; i++) {
        loc[i] = s;
        s += g_cnt[base + i];
        g_cur[base + i] = 0;
    }
    sums[tid] = s;
    __syncthreads();
    for (int off = 1; off < 1024; off <<= 1) {
        int v = (tid >= off) ? sums[tid - off] : 0;
        __syncthreads();
        sums[tid] += v;
        __syncthreads();
    }
    int excl = (tid > 0) ? sums[tid - 1] : 0;
#pragma unroll
    for (int i = 0; i < 16; i++) g_indptr[base + i] = excl + loc[i];
    if (tid == 1023) g_indptr[NN] = sums[1023];
}

__global__ void k_scatter(const int* __restrict__ src, const int* __restrict__ dst) {
    int i = blockIdx.x * blockDim.x + threadIdx.x;
    if (i < EE) {
        int d = dst[i];
        int p = g_indptr[d] + atomicAdd(&g_cur[d], 1);
        g_esrc[p] = src[i];
    }
}

// ---------------- SGEMM: C[M,Nc] = A[M,K] @ B[K,Nc] (row-major, fp32) ----------------
// use_ext: A = Aext if 1 else g_y.   which: C = g_h if 0 else g_r.
__global__ void __launch_bounds__(256) k_sgemm(const float* __restrict__ Aext, int use_ext,
                                               const float* __restrict__ B, int which,
                                               int K, int Nc) {
    const float* A = use_ext ? Aext : g_y;
    float* C = which == 0 ? g_h : g_r;
    const int BM = 128, BN = 128, BK = 8;
    __shared__ float As[BK][BM];
    __shared__ float Bs[BK][BN];
    int tid = threadIdx.x;
    int rowT = blockIdx.y * BM;
    int colT = blockIdx.x * BN;

    int aRow = tid >> 1;            // 0..127
    int aCol = (tid & 1) * 4;       // 0 or 4
    int bRow = tid >> 5;            // 0..7
    int bCol = (tid & 31) * 4;      // 0..124

    int tx = tid & 15;              // 0..15 -> 8 cols each
    int ty = tid >> 4;              // 0..15 -> 8 rows each

    float acc[8][8];
#pragma unroll
    for (int i = 0; i < 8; i++)
#pragma unroll
        for (int j = 0; j < 8; j++) acc[i][j] = 0.f;

    for (int kt = 0; kt < K; kt += BK) {
        float4 a4 = *reinterpret_cast<const float4*>(A + (size_t)(rowT + aRow) * K + kt + aCol);
        As[aCol + 0][aRow] = a4.x;
        As[aCol + 1][aRow] = a4.y;
        As[aCol + 2][aRow] = a4.z;
        As[aCol + 3][aRow] = a4.w;
        float4 b4 = *reinterpret_cast<const float4*>(B + (size_t)(kt + bRow) * Nc + colT + bCol);
        *reinterpret_cast<float4*>(&Bs[bRow][bCol]) = b4;
        __syncthreads();
#pragma unroll
        for (int k = 0; k < BK; k++) {
            float4 ra0 = *reinterpret_cast<const float4*>(&As[k][ty * 8]);
            float4 ra1 = *reinterpret_cast<const float4*>(&As[k][ty * 8 + 4]);
            float4 rb0 = *reinterpret_cast<const float4*>(&Bs[k][tx * 8]);
            float4 rb1 = *reinterpret_cast<const float4*>(&Bs[k][tx * 8 + 4]);
            float ra[8] = {ra0.x, ra0.y, ra0.z, ra0.w, ra1.x, ra1.y, ra1.z, ra1.w};
            float rb[8] = {rb0.x, rb0.y, rb0.z, rb0.w, rb1.x, rb1.y, rb1.z, rb1.w};
#pragma unroll
            for (int i = 0; i < 8; i++)
#pragma unroll
                for (int j = 0; j < 8; j++) acc[i][j] = fmaf(ra[i], rb[j], acc[i][j]);
        }
        __syncthreads();
    }
#pragma unroll
    for (int i = 0; i < 8; i++) {
        float* cr = C + (size_t)(rowT + ty * 8 + i) * Nc + colT + tx * 8;
        *reinterpret_cast<float4*>(cr) = make_float4(acc[i][0], acc[i][1], acc[i][2], acc[i][3]);
        *reinterpret_cast<float4*>(cr + 4) = make_float4(acc[i][4], acc[i][5], acc[i][6], acc[i][7]);
    }
}

// ---------------- attention projections el/er ----------------
__global__ void k_attn(const float* __restrict__ al, const float* __restrict__ ar, int d) {
    int gw = (blockIdx.x * blockDim.x + threadIdx.x) >> 5;
    int lane = threadIdx.x & 31;
    if (gw >= NN * HH) return;
    int n = gw >> 1, hd = gw & 1;
    const float* hr = g_h + (size_t)n * (2 * d) + hd * d;
    const float* av = al + hd * d;
    const float* bv = ar + hd * d;
    float sl = 0.f, sr = 0.f;
    for (int c = lane; c < d; c += 32) {
        float v = hr[c];
        sl = fmaf(v, av[c], sl);
        sr = fmaf(v, bv[c], sr);
    }
#pragma unroll
    for (int o = 16; o > 0; o >>= 1) {
        sl += __shfl_down_sync(0xffffffffu, sl, o);
        sr += __shfl_down_sync(0xffffffffu, sr, o);
    }
    if (lane == 0) { g_el[gw] = sl; g_er[gw] = sr; }
}

// ---------------- per-dst softmax + weighted aggregation (+ residual) ----------------
__global__ void __launch_bounds__(256) k_agg(int d) {
    const int HD = 2 * d;
    int n = blockIdx.x;
    int tid = threadIdx.x;
    int start = g_indptr[n];
    int deg = g_indptr[n + 1] - start;
    __shared__ float s_m0, s_m1, s_i0, s_i1;
    __shared__ int s_src[32];
    __shared__ float s_w[32][2];
    float er0 = g_er[n * 2 + 0];
    float er1 = g_er[n * 2 + 1];

    if (tid < 32) {
        float m0 = -1e30f, m1 = -1e30f;
        for (int j = tid; j < deg; j += 32) {
            int s = g_esrc[start + j];
            float e0 = lrelu(g_el[s * 2 + 0] + er0, 0.2f);
            float e1 = lrelu(g_el[s * 2 + 1] + er1, 0.2f);
            m0 = fmaxf(m0, e0); m1 = fmaxf(m1, e1);
        }
#pragma unroll
        for (int o = 16; o > 0; o >>= 1) {
            m0 = fmaxf(m0, __shfl_xor_sync(0xffffffffu, m0, o));
            m1 = fmaxf(m1, __shfl_xor_sync(0xffffffffu, m1, o));
        }
        float z0 = 0.f, z1 = 0.f;
        for (int j = tid; j < deg; j += 32) {
            int s = g_esrc[start + j];
            float e0 = lrelu(g_el[s * 2 + 0] + er0, 0.2f);
            float e1 = lrelu(g_el[s * 2 + 1] + er1, 0.2f);
            z0 += expf(e0 - m0);
            z1 += expf(e1 - m1);
        }
#pragma unroll
        for (int o = 16; o > 0; o >>= 1) {
            z0 += __shfl_xor_sync(0xffffffffu, z0, o);
            z1 += __shfl_xor_sync(0xffffffffu, z1, o);
        }
        if (tid == 0) {
            s_m0 = m0; s_m1 = m1;
            s_i0 = (deg > 0) ? 1.f / z0 : 0.f;
            s_i1 = (deg > 0) ? 1.f / z1 : 0.f;
        }
    }
    __syncthreads();
    float m0 = s_m0, m1 = s_m1, i0 = s_i0, i1 = s_i1;

    float acc[4] = {0.f, 0.f, 0.f, 0.f};
    for (int c0 = 0; c0 < deg; c0 += 32) {
        int cn = min(32, deg - c0);
        if (tid < cn) {
            int s = g_esrc[start + c0 + tid];
            s_src[tid] = s;
            float e0 = lrelu(g_el[s * 2 + 0] + er0, 0.2f);
            float e1 = lrelu(g_el[s * 2 + 1] + er1, 0.2f);
            s_w[tid][0] = expf(e0 - m0) * i0;
            s_w[tid][1] = expf(e1 - m1) * i1;
        }
        __syncthreads();
        for (int j = 0; j < cn; j++) {
            const float* hr = g_h + (size_t)s_src[j] * HD;
            float w0 = s_w[j][0], w1 = s_w[j][1];
#pragma unroll
            for (int k = 0; k < 4; k++) {
                int c = tid + k * 256;
                if (c < HD) {
                    float w = (c < d) ? w0 : w1;
                    acc[k] = fmaf(w, __ldg(hr + c), acc[k]);
                }
            }
        }
        __syncthreads();
    }
#pragma unroll
    for (int k = 0; k < 4; k++) {
        int c = tid + k * 256;
        if (c < HD) g_x[(size_t)n * HD + c] = acc[k] + g_r[(size_t)n * HD + c];
    }
}

// ---------------- GraphNorm stats ----------------
__global__ void k_zstats() {
    int c = threadIdx.x;
    if (c < MAXD) { g_s1[c] = 0.f; g_s2[c] = 0.f; }
}

__global__ void k_colstats(int d) {
    int r0 = blockIdx.x * 128;  // rows of [NN*HH, d]
    int c0 = threadIdx.x, c1 = threadIdx.x + 256;
    float a0 = 0.f, b0 = 0.f, a1 = 0.f, b1 = 0.f;
    for (int r = 0; r < 128; r++) {
        const float* row = g_x + (size_t)(r0 + r) * d;
        if (c0 < d) { float v = row[c0]; a0 += v; b0 += v * v; }
        if (c1 < d) { float v = row[c1]; a1 += v; b1 += v * v; }
    }
    if (c0 < d) { atomicAdd(&g_s1[c0], a0); atomicAdd(&g_s2[c0], b0); }
    if (c1 < d) { atomicAdd(&g_s1[c1], a1); atomicAdd(&g_s2[c1], b1); }
}

__global__ void k_finstats(const float* __restrict__ gamma, const float* __restrict__ beta,
                           const float* __restrict__ alpha, int d) {
    int c = blockIdx.x * blockDim.x + threadIdx.x;
    if (c >= d) return;
    const float inv_nh = 1.f / (float)(NN * HH);
    float mean = g_s1[c] * inv_nh;
    float ex2 = g_s2[c] * inv_nh;
    float a = alpha[c];
    float var = ex2 - 2.f * a * mean * mean + a * a * mean * mean;
    float inv = rsqrtf(var + 1e-5f);
    float sc = gamma[c] * inv;
    g_scale[c] = sc;
    g_bias[c] = beta[c] - sc * a * mean;
}

// ---------------- normalize + lrelu + head-mean partials ----------------
__global__ void k_norm(const int* __restrict__ gid, int d, int off) {
    int nb = blockIdx.x * 64;
    int g = gid[nb];  // nodes per graph = 1024, block spans 64 nodes of one graph
    int c0 = threadIdx.x, c1 = threadIdx.x + 256;
    float acc0 = 0.f, acc1 = 0.f;
    float sc0 = 0.f, bi0 = 0.f, sc1 = 0.f, bi1 = 0.f;
    if (c0 < d) { sc0 = g_scale[c0]; bi0 = g_bias[c0]; }
    if (c1 < d) { sc1 = g_scale[c1]; bi1 = g_bias[c1]; }
    for (int i = 0; i < 64; i++) {
        size_t base = (size_t)(nb + i) * 2 * d;
        if (c0 < d) {
            float y0 = lrelu(g_x[base + c0] * sc0 + bi0, 0.01f);
            float y1 = lrelu(g_x[base + d + c0] * sc0 + bi0, 0.01f);
            g_y[base + c0] = y0;
            g_y[base + d + c0] = y1;
            acc0 += y0 + y1;
        }
        if (c1 < d) {
            float y0 = lrelu(g_x[base + c1] * sc1 + bi1, 0.01f);
            float y1 = lrelu(g_x[base + d + c1] * sc1 + bi1, 0.01f);
            g_y[base + c1] = y0;
            g_y[base + d + c1] = y1;
            acc1 += y0 + y1;
        }
    }
    if (c0 < d) atomicAdd(&g_parts[g * OUTC + off + c0], acc0);
    if (c1 < d) atomicAdd(&g_parts[g * OUTC + off + c1], acc1);
}

// ---------------- final: divide + lrelu ----------------
__global__ void k_final(float* __restrict__ out) {
    int i = blockIdx.x * blockDim.x + threadIdx.x;
    if (i < BB * OUTC) {
        int b = i / OUTC;
        float v = g_parts[i] / (2.f * (float)g_counts[b]);  // /H, /counts
        out[i] = lrelu(v, 0.01f);
    }
}

// ---------------- launch ----------------
extern "C" void kernel_launch(void* const* d_in, const int* in_sizes, int n_in,
                              void* d_out, int out_size) {
    const float* nf = (const float*)d_in[0];
    const float* W[3]  = {(const float*)d_in[1],  (const float*)d_in[8],  (const float*)d_in[15]};
    const float* AL[3] = {(const float*)d_in[2],  (const float*)d_in[9],  (const float*)d_in[16]};
    const float* AR[3] = {(const float*)d_in[3],  (const float*)d_in[10], (const float*)d_in[17]};
    const float* RW[3] = {(const float*)d_in[4],  (const float*)d_in[11], (const float*)d_in[18]};
    const float* GA[3] = {(const float*)d_in[5],  (const float*)d_in[12], (const float*)d_in[19]};
    const float* BE[3] = {(const float*)d_in[6],  (const float*)d_in[13], (const float*)d_in[20]};
    const float* AP[3] = {(const float*)d_in[7],  (const float*)d_in[14], (const float*)d_in[21]};
    const int* src = (const int*)d_in[22];
    const int* dst = (const int*)d_in[23];
    const int* gid = (const int*)d_in[24];
    float* out = (float*)d_out;

    k_zero_front<<<(NN + 255) / 256, 256>>>();
    k_counts<<<NN / 256, 256>>>(gid);
    k_hist<<<EE / 256, 256>>>(dst);
    k_scan<<<1, 1024>>>();
    k_scatter<<<EE / 256, 256>>>(src, dst);

    const int dims[3] = {128, 256, 512};
    const int offs[3] = {0, 128, 384};
    for (int l = 0; l < 3; l++) {
        int d = dims[l], in = d, HD = 2 * d;
        int use_ext = (l == 0) ? 1 : 0;
        dim3 gg(HD / 128, NN / 128);
        k_sgemm<<<gg, 256>>>(nf, use_ext, W[l], 0, in, HD);
        k_sgemm<<<gg, 256>>>(nf, use_ext, RW[l], 1, in, HD);
        k_attn<<<(NN * HH * 32) / 256, 256>>>(AL[l], AR[l], d);
        k_agg<<<NN, 256>>>(d);
        k_zstats<<<1, MAXD>>>();
        k_colstats<<<(NN * HH) / 128, 256>>>(d);
        k_finstats<<<(d + 255) / 256, 256>>>(GA[l], BE[l], AP[l], d);
        k_norm<<<NN / 64, 256>>>(gid, d, offs[l]);
    }
    k_final<<<(BB * OUTC + 255) / 256, 256>>>(out);
}

// round 4
// speedup vs baseline: 1.9417x; 1.9417x over previous
#include <cuda_runtime.h>
#include <math.h>
#include <stdint.h>

#define NN 16384
#define EE 131072
#define BB 16
#define HH 2
#define MAXD 512
#define MAXHD 1024
#define OUTC 896

// ---------------- scratch (device globals; no allocation) ----------------
__device__ float g_x[(size_t)NN * MAXHD];   // raw GAT output per layer
__device__ float g_y[(size_t)NN * MAXHD];   // normalized output (next layer input)
__device__ float g_h[(size_t)NN * MAXHD];   // h = x @ W
__device__ float g_r[(size_t)NN * MAXHD];   // res = x @ rW
__device__ float g_el[NN * HH];
__device__ float g_er[NN * HH];
__device__ int   g_indptr[NN + 1];
__device__ int   g_cnt[NN];
__device__ int   g_cur[NN];
__device__ int   g_esrc[EE];
__device__ float g_s1[MAXD];
__device__ float g_s2[MAXD];
__device__ float g_scale[MAXD];
__device__ float g_bias[MAXD];
__device__ float g_parts[BB * OUTC];
__device__ int   g_counts[BB];

__device__ __forceinline__ float lrelu(float v, float s) { return v > 0.f ? v : s * v; }

__device__ __forceinline__ float to_tf32(float x) {
    uint32_t r;
    asm("cvt.rna.tf32.f32 %0, %1;" : "=r"(r) : "f"(x));
    return __uint_as_float(r);
}

// ---------------- misc zero / histogram / CSR ----------------
__global__ void k_zero_front() {
    int i = blockIdx.x * blockDim.x + threadIdx.x;
    if (i < BB * OUTC) g_parts[i] = 0.f;
    if (i < BB) g_counts[i] = 0;
    if (i < NN) g_cnt[i] = 0;
}

__global__ void k_counts(const int* __restrict__ gid) {
    int i = blockIdx.x * blockDim.x + threadIdx.x;
    if (i < NN) atomicAdd(&g_counts[gid[i]], 1);
}

__global__ void k_hist(const int* __restrict__ dst) {
    int i = blockIdx.x * blockDim.x + threadIdx.x;
    if (i < EE) atomicAdd(&g_cnt[dst[i]], 1);
}

__global__ void k_scan() {  // one block, 1024 threads; NN = 1024*16
    __shared__ int sums[1024];
    int tid = threadIdx.x;
    int base = tid * 16;
    int loc[16];
    int s = 0;
#pragma unroll
    for (int i = 0; i < 16; i++) {
        loc[i] = s;
        s += g_cnt[base + i];
        g_cur[base + i] = 0;
    }
    sums[tid] = s;
    __syncthreads();
    for (int off = 1; off < 1024; off <<= 1) {
        int v = (tid >= off) ? sums[tid - off] : 0;
        __syncthreads();
        sums[tid] += v;
        __syncthreads();
    }
    int excl = (tid > 0) ? sums[tid - 1] : 0;
#pragma unroll
    for (int i = 0; i < 16; i++) g_indptr[base + i] = excl + loc[i];
    if (tid == 1023) g_indptr[NN] = sums[1023];
}

__global__ void k_scatter(const int* __restrict__ src, const int* __restrict__ dst) {
    int i = blockIdx.x * blockDim.x + threadIdx.x;
    if (i < EE) {
        int d = dst[i];
        int p = g_indptr[d] + atomicAdd(&g_cur[d], 1);
        g_esrc[p] = src[i];
    }
}

// ---------------- TF32 tensor-core GEMM: C[M,Nc] = A[M,K] @ B[K,Nc] ----------------
// Block tile 128x128, BK=32. 8 warps: 4 (m) x 2 (n), warp tile 32x64.
// mma.sync.aligned.m16n8k8.row.col.f32.tf32.tf32.f32
// use_ext: A = Aext if 1 else g_y.   which: C = g_h if 0 else g_r.
__global__ void __launch_bounds__(256) k_mma(const float* __restrict__ Aext, int use_ext,
                                             const float* __restrict__ B, int which,
                                             int K, int Nc) {
    const float* A = use_ext ? Aext : g_y;
    float* C = (which == 0) ? g_h : g_r;

    __shared__ float As[128][36];   // [m][k], stride 36 -> conflict-free frag loads
    __shared__ float Bs[32][136];   // [k][n], stride 136

    int tid = threadIdx.x;
    int lane = tid & 31;
    int warp = tid >> 5;
    int wm = (warp >> 1) * 32;      // warp m-offset within block tile (0..96)
    int wn = (warp & 1) * 64;       // warp n-offset (0 or 64)
    int rowT = blockIdx.y * 128;
    int colT = blockIdx.x * 128;

    int gr = lane >> 2;             // 0..7 (group)
    int tg = lane & 3;              // 0..3 (thread-in-group)

    float acc[2][8][4];
#pragma unroll
    for (int i = 0; i < 2; i++)
#pragma unroll
        for (int j = 0; j < 8; j++)
#pragma unroll
            for (int c = 0; c < 4; c++) acc[i][j][c] = 0.f;

    int aRow = tid >> 3;            // 0..31 (step 32 over 128 rows)
    int aCol = (tid & 7) * 4;       // 0..28
    int bRow = tid >> 6;            // 0..3
    int bCol = (tid & 63) * 2;      // 0..126, float2 per thread

    for (int kt = 0; kt < K; kt += 32) {
#pragma unroll
        for (int p = 0; p < 4; p++) {
            int r = aRow + p * 32;
            float4 a4 = *reinterpret_cast<const float4*>(A + (size_t)(rowT + r) * K + kt + aCol);
            As[r][aCol + 0] = to_tf32(a4.x);
            As[r][aCol + 1] = to_tf32(a4.y);
            As[r][aCol + 2] = to_tf32(a4.z);
            As[r][aCol + 3] = to_tf32(a4.w);
        }
#pragma unroll
        for (int p = 0; p < 8; p++) {
            int r = bRow + p * 4;
            float2 b2 = *reinterpret_cast<const float2*>(B + (size_t)(kt + r) * Nc + colT + bCol);
            Bs[r][bCol + 0] = to_tf32(b2.x);
            Bs[r][bCol + 1] = to_tf32(b2.y);
        }
        __syncthreads();

#pragma unroll
        for (int kk = 0; kk < 32; kk += 8) {
            float af[2][4];
#pragma unroll
            for (int i = 0; i < 2; i++) {
                int m0 = wm + i * 16 + gr;
                af[i][0] = As[m0][kk + tg];
                af[i][1] = As[m0 + 8][kk + tg];
                af[i][2] = As[m0][kk + tg + 4];
                af[i][3] = As[m0 + 8][kk + tg + 4];
            }
            float bf[8][2];
#pragma unroll
            for (int j = 0; j < 8; j++) {
                int n0 = wn + j * 8 + gr;
                bf[j][0] = Bs[kk + tg][n0];
                bf[j][1] = Bs[kk + tg + 4][n0];
            }
#pragma unroll
            for (int i = 0; i < 2; i++)
#pragma unroll
                for (int j = 0; j < 8; j++) {
                    asm volatile(
                        "mma.sync.aligned.m16n8k8.row.col.f32.tf32.tf32.f32 "
                        "{%0,%1,%2,%3},{%4,%5,%6,%7},{%8,%9},{%0,%1,%2,%3};"
                        : "+f"(acc[i][j][0]), "+f"(acc[i][j][1]),
                          "+f"(acc[i][j][2]), "+f"(acc[i][j][3])
                        : "r"(__float_as_uint(af[i][0])), "r"(__float_as_uint(af[i][1])),
                          "r"(__float_as_uint(af[i][2])), "r"(__float_as_uint(af[i][3])),
                          "r"(__float_as_uint(bf[j][0])), "r"(__float_as_uint(bf[j][1])));
                }
        }
        __syncthreads();
    }

    // epilogue: c0,c1 at (row, 2*tg), (row, 2*tg+1); c2,c3 at row+8
#pragma unroll
    for (int i = 0; i < 2; i++) {
        int r0 = rowT + wm + i * 16 + gr;
#pragma unroll
        for (int j = 0; j < 8; j++) {
            int ccol = colT + wn + j * 8 + tg * 2;
            *reinterpret_cast<float2*>(C + (size_t)r0 * Nc + ccol) =
                make_float2(acc[i][j][0], acc[i][j][1]);
            *reinterpret_cast<float2*>(C + (size_t)(r0 + 8) * Nc + ccol) =
                make_float2(acc[i][j][2], acc[i][j][3]);
        }
    }
}

// ---------------- attention projections el/er ----------------
__global__ void k_attn(const float* __restrict__ al, const float* __restrict__ ar, int d) {
    int gw = (blockIdx.x * blockDim.x + threadIdx.x) >> 5;
    int lane = threadIdx.x & 31;
    if (gw >= NN * HH) return;
    int n = gw >> 1, hd = gw & 1;
    const float* hr = g_h + (size_t)n * (2 * d) + hd * d;
    const float* av = al + hd * d;
    const float* bv = ar + hd * d;
    float sl = 0.f, sr = 0.f;
    for (int c = lane; c < d; c += 32) {
        float v = hr[c];
        sl = fmaf(v, av[c], sl);
        sr = fmaf(v, bv[c], sr);
    }
#pragma unroll
    for (int o = 16; o > 0; o >>= 1) {
        sl += __shfl_down_sync(0xffffffffu, sl, o);
        sr += __shfl_down_sync(0xffffffffu, sr, o);
    }
    if (lane == 0) { g_el[gw] = sl; g_er[gw] = sr; }
}

// ---------------- per-dst softmax + weighted aggregation (+ residual) ----------------
__global__ void __launch_bounds__(256) k_agg(int d) {
    const int HD = 2 * d;
    int n = blockIdx.x;
    int tid = threadIdx.x;
    int start = g_indptr[n];
    int deg = g_indptr[n + 1] - start;
    __shared__ float s_m0, s_m1, s_i0, s_i1;
    __shared__ int s_src[32];
    __shared__ float s_w[32][2];
    float er0 = g_er[n * 2 + 0];
    float er1 = g_er[n * 2 + 1];

    if (tid < 32) {
        float m0 = -1e30f, m1 = -1e30f;
        for (int j = tid; j < deg; j += 32) {
            int s = g_esrc[start + j];
            float e0 = lrelu(g_el[s * 2 + 0] + er0, 0.2f);
            float e1 = lrelu(g_el[s * 2 + 1] + er1, 0.2f);
            m0 = fmaxf(m0, e0); m1 = fmaxf(m1, e1);
        }
#pragma unroll
        for (int o = 16; o > 0; o >>= 1) {
            m0 = fmaxf(m0, __shfl_xor_sync(0xffffffffu, m0, o));
            m1 = fmaxf(m1, __shfl_xor_sync(0xffffffffu, m1, o));
        }
        float z0 = 0.f, z1 = 0.f;
        for (int j = tid; j < deg; j += 32) {
            int s = g_esrc[start + j];
            float e0 = lrelu(g_el[s * 2 + 0] + er0, 0.2f);
            float e1 = lrelu(g_el[s * 2 + 1] + er1, 0.2f);
            z0 += expf(e0 - m0);
            z1 += expf(e1 - m1);
        }
#pragma unroll
        for (int o = 16; o > 0; o >>= 1) {
            z0 += __shfl_xor_sync(0xffffffffu, z0, o);
            z1 += __shfl_xor_sync(0xffffffffu, z1, o);
        }
        if (tid == 0) {
            s_m0 = m0; s_m1 = m1;
            s_i0 = (deg > 0) ? 1.f / z0 : 0.f;
            s_i1 = (deg > 0) ? 1.f / z1 : 0.f;
        }
    }
    __syncthreads();
    float m0 = s_m0, m1 = s_m1, i0 = s_i0, i1 = s_i1;

    float acc[4] = {0.f, 0.f, 0.f, 0.f};
    for (int c0 = 0; c0 < deg; c0 += 32) {
        int cn = min(32, deg - c0);
        if (tid < cn) {
            int s = g_esrc[start + c0 + tid];
            s_src[tid] = s;
            float e0 = lrelu(g_el[s * 2 + 0] + er0, 0.2f);
            float e1 = lrelu(g_el[s * 2 + 1] + er1, 0.2f);
            s_w[tid][0] = expf(e0 - m0) * i0;
            s_w[tid][1] = expf(e1 - m1) * i1;
        }
        __syncthreads();
        for (int j = 0; j < cn; j++) {
            const float* hr = g_h + (size_t)s_src[j] * HD;
            float w0 = s_w[j][0], w1 = s_w[j][1];
#pragma unroll
            for (int k = 0; k < 4; k++) {
                int c = tid + k * 256;
                if (c < HD) {
                    float w = (c < d) ? w0 : w1;
                    acc[k] = fmaf(w, __ldg(hr + c), acc[k]);
                }
            }
        }
        __syncthreads();
    }
#pragma unroll
    for (int k = 0; k < 4; k++) {
        int c = tid + k * 256;
        if (c < HD) g_x[(size_t)n * HD + c] = acc[k] + g_r[(size_t)n * HD + c];
    }
}

// ---------------- GraphNorm stats ----------------
__global__ void k_zstats() {
    int c = threadIdx.x;
    if (c < MAXD) { g_s1[c] = 0.f; g_s2[c] = 0.f; }
}

__global__ void k_colstats(int d) {
    int r0 = blockIdx.x * 128;  // rows of [NN*HH, d]
    int c0 = threadIdx.x, c1 = threadIdx.x + 256;
    float a0 = 0.f, b0 = 0.f, a1 = 0.f, b1 = 0.f;
    for (int r = 0; r < 128; r++) {
        const float* row = g_x + (size_t)(r0 + r) * d;
        if (c0 < d) { float v = row[c0]; a0 += v; b0 += v * v; }
        if (c1 < d) { float v = row[c1]; a1 += v; b1 += v * v; }
    }
    if (c0 < d) { atomicAdd(&g_s1[c0], a0); atomicAdd(&g_s2[c0], b0); }
    if (c1 < d) { atomicAdd(&g_s1[c1], a1); atomicAdd(&g_s2[c1], b1); }
}

__global__ void k_finstats(const float* __restrict__ gamma, const float* __restrict__ beta,
                           const float* __restrict__ alpha, int d) {
    int c = blockIdx.x * blockDim.x + threadIdx.x;
    if (c >= d) return;
    const float inv_nh = 1.f / (float)(NN * HH);
    float mean = g_s1[c] * inv_nh;
    float ex2 = g_s2[c] * inv_nh;
    float a = alpha[c];
    float var = ex2 - 2.f * a * mean * mean + a * a * mean * mean;
    float inv = rsqrtf(var + 1e-5f);
    float sc = gamma[c] * inv;
    g_scale[c] = sc;
    g_bias[c] = beta[c] - sc * a * mean;
}

// ---------------- normalize + lrelu + head-mean partials ----------------
__global__ void k_norm(const int* __restrict__ gid, int d, int off) {
    int nb = blockIdx.x * 64;
    int g = gid[nb];  // nodes per graph = 1024, block spans 64 nodes of one graph
    int c0 = threadIdx.x, c1 = threadIdx.x + 256;
    float acc0 = 0.f, acc1 = 0.f;
    float sc0 = 0.f, bi0 = 0.f, sc1 = 0.f, bi1 = 0.f;
    if (c0 < d) { sc0 = g_scale[c0]; bi0 = g_bias[c0]; }
    if (c1 < d) { sc1 = g_scale[c1]; bi1 = g_bias[c1]; }
    for (int i = 0; i < 64; i++) {
        size_t base = (size_t)(nb + i) * 2 * d;
        if (c0 < d) {
            float y0 = lrelu(g_x[base + c0] * sc0 + bi0, 0.01f);
            float y1 = lrelu(g_x[base + d + c0] * sc0 + bi0, 0.01f);
            g_y[base + c0] = y0;
            g_y[base + d + c0] = y1;
            acc0 += y0 + y1;
        }
        if (c1 < d) {
            float y0 = lrelu(g_x[base + c1] * sc1 + bi1, 0.01f);
            float y1 = lrelu(g_x[base + d + c1] * sc1 + bi1, 0.01f);
            g_y[base + c1] = y0;
            g_y[base + d + c1] = y1;
            acc1 += y0 + y1;
        }
    }
    if (c0 < d) atomicAdd(&g_parts[g * OUTC + off + c0], acc0);
    if (c1 < d) atomicAdd(&g_parts[g * OUTC + off + c1], acc1);
}

// ---------------- final: divide + lrelu ----------------
__global__ void k_final(float* __restrict__ out) {
    int i = blockIdx.x * blockDim.x + threadIdx.x;
    if (i < BB * OUTC) {
        int b = i / OUTC;
        float v = g_parts[i] / (2.f * (float)g_counts[b]);  // /H, /counts
        out[i] = lrelu(v, 0.01f);
    }
}

// ---------------- launch ----------------
extern "C" void kernel_launch(void* const* d_in, const int* in_sizes, int n_in,
                              void* d_out, int out_size) {
    const float* nf = (const float*)d_in[0];
    const float* W[3]  = {(const float*)d_in[1],  (const float*)d_in[8],  (const float*)d_in[15]};
    const float* AL[3] = {(const float*)d_in[2],  (const float*)d_in[9],  (const float*)d_in[16]};
    const float* AR[3] = {(const float*)d_in[3],  (const float*)d_in[10], (const float*)d_in[17]};
    const float* RW[3] = {(const float*)d_in[4],  (const float*)d_in[11], (const float*)d_in[18]};
    const float* GA[3] = {(const float*)d_in[5],  (const float*)d_in[12], (const float*)d_in[19]};
    const float* BE[3] = {(const float*)d_in[6],  (const float*)d_in[13], (const float*)d_in[20]};
    const float* AP[3] = {(const float*)d_in[7],  (const float*)d_in[14], (const float*)d_in[21]};
    const int* src = (const int*)d_in[22];
    const int* dst = (const int*)d_in[23];
    const int* gid = (const int*)d_in[24];
    float* out = (float*)d_out;

    k_zero_front<<<(NN + 255) / 256, 256>>>();
    k_counts<<<NN / 256, 256>>>(gid);
    k_hist<<<EE / 256, 256>>>(dst);
    k_scan<<<1, 1024>>>();
    k_scatter<<<EE / 256, 256>>>(src, dst);

    const int dims[3] = {128, 256, 512};
    const int offs[3] = {0, 128, 384};
    for (int l = 0; l < 3; l++) {
        int d = dims[l], in = d, HD = 2 * d;
        int use_ext = (l == 0) ? 1 : 0;
        dim3 gg(HD / 128, NN / 128);
        k_mma<<<gg, 256>>>(nf, use_ext, W[l], 0, in, HD);
        k_mma<<<gg, 256>>>(nf, use_ext, RW[l], 1, in, HD);
        k_attn<<<(NN * HH * 32) / 256, 256>>>(AL[l], AR[l], d);
        k_agg<<<NN, 256>>>(d);
        k_zstats<<<1, MAXD>>>();
        k_colstats<<<(NN * HH) / 128, 256>>>(d);
        k_finstats<<<(d + 255) / 256, 256>>>(GA[l], BE[l], AP[l], d);
        k_norm<<<NN / 64, 256>>>(gid, d, offs[l]);
    }
    k_final<<<(BB * OUTC + 255) / 256, 256>>>(out);
}

// round 6
// speedup vs baseline: 2.0231x; 1.0419x over previous
#include <cuda_runtime.h>
#include <math.h>
#include <stdint.h>

#define NN 16384
#define EE 131072
#define BB 16
#define HH 2
#define MAXD 512
#define MAXHD 1024
#define OUTC 896

// ---------------- scratch (device globals; no allocation) ----------------
__device__ float g_x[(size_t)NN * MAXHD];
__device__ float g_y[(size_t)NN * MAXHD];
__device__ float g_h[(size_t)NN * MAXHD];
__device__ float g_r[(size_t)NN * MAXHD];
__device__ float g_el[NN * HH];
__device__ float g_er[NN * HH];
__device__ int   g_indptr[NN + 1];
__device__ int   g_cnt[NN];
__device__ int   g_cur[NN];
__device__ int   g_esrc[EE];
__device__ int   g_bsum[64];
__device__ int   g_boff[64];
__device__ float g_s1[MAXD];
__device__ float g_s2[MAXD];
__device__ float g_scale[MAXD];
__device__ float g_bias[MAXD];
__device__ float g_parts[BB * OUTC];
__device__ int   g_counts[BB];

__device__ __forceinline__ float lrelu(float v, float s) { return v > 0.f ? v : s * v; }

__device__ __forceinline__ void cp_async16(uint32_t saddr, const void* gptr) {
    asm volatile("cp.async.cg.shared.global [%0], [%1], 16;" :: "r"(saddr), "l"(gptr));
}
__device__ __forceinline__ void cp_commit() { asm volatile("cp.async.commit_group;"); }

// ---------------- front: zero + hist/counts + parallel scan + scatter ----------------
__global__ void k_zero() {
    int i = blockIdx.x * blockDim.x + threadIdx.x;
    if (i < BB * OUTC) g_parts[i] = 0.f;
    if (i < BB) g_counts[i] = 0;
    if (i < NN) g_cnt[i] = 0;
}

__global__ void k_build(const int* __restrict__ dst, const int* __restrict__ gid) {
    int i = blockIdx.x * blockDim.x + threadIdx.x;
    if (i < EE) atomicAdd(&g_cnt[dst[i]], 1);
    if (i < NN) atomicAdd(&g_counts[gid[i]], 1);
}

__global__ void k_scan1() {  // 64 blocks x 256
    __shared__ int sm[256];
    int tid = threadIdx.x;
    int i = blockIdx.x * 256 + tid;
    int v = g_cnt[i];
    sm[tid] = v;
    __syncthreads();
    for (int off = 1; off < 256; off <<= 1) {
        int t = (tid >= off) ? sm[tid - off] : 0;
        __syncthreads();
        sm[tid] += t;
        __syncthreads();
    }
    g_indptr[i] = sm[tid] - v;          // local exclusive
    g_cur[i] = 0;
    if (tid == 255) g_bsum[blockIdx.x] = sm[255];
}

__global__ void k_scan2() {  // 1 block x 64
    __shared__ int sm[64];
    int tid = threadIdx.x;
    int v = g_bsum[tid];
    sm[tid] = v;
    __syncthreads();
    for (int off = 1; off < 64; off <<= 1) {
        int t = (tid >= off) ? sm[tid - off] : 0;
        __syncthreads();
        sm[tid] += t;
        __syncthreads();
    }
    g_boff[tid] = sm[tid] - v;
    if (tid == 63) g_indptr[NN] = sm[63];
}

__global__ void k_scan3() {
    int i = blockIdx.x * blockDim.x + threadIdx.x;
    if (i < NN) g_indptr[i] += g_boff[i >> 8];
}

__global__ void k_scatter(const int* __restrict__ src, const int* __restrict__ dst) {
    int i = blockIdx.x * blockDim.x + threadIdx.x;
    if (i < EE) {
        int d = dst[i];
        int p = g_indptr[d] + atomicAdd(&g_cur[d], 1);
        g_esrc[p] = src[i];
    }
}

// ---------------- TF32 tensor-core GEMM, cp.async double-buffered ----------------
// C[M,Nc] = A[M,K] @ B[K,Nc]. Block 128x128, BK=16, 2 stages.
// blockIdx.z: 0 -> B=W, C=g_h; 1 -> B=rW, C=g_r.
__global__ void __launch_bounds__(256) k_mma(const float* __restrict__ Aext, int use_ext,
                                             const float* __restrict__ Bw,
                                             const float* __restrict__ Br,
                                             int K, int Nc) {
    const float* A = use_ext ? Aext : g_y;
    const float* B = blockIdx.z ? Br : Bw;
    float* C = blockIdx.z ? g_r : g_h;

    __shared__ float As[2][128][20];
    __shared__ float Bs[2][16][136];

    int tid = threadIdx.x;
    int lane = tid & 31;
    int warp = tid >> 5;
    int wm = (warp >> 1) * 32;
    int wn = (warp & 1) * 64;
    int rowT = blockIdx.y * 128;
    int colT = blockIdx.x * 128;
    int gr = lane >> 2;
    int tg = lane & 3;

    int aRow = tid >> 2;            // 0..63
    int aCol = (tid & 3) * 4;       // 0,4,8,12
    int bRow = tid >> 5;            // 0..7
    int bCol = (tid & 31) * 4;      // 0..124

    float acc[2][8][4];
#pragma unroll
    for (int i = 0; i < 2; i++)
#pragma unroll
        for (int j = 0; j < 8; j++)
#pragma unroll
            for (int c = 0; c < 4; c++) acc[i][j][c] = 0.f;

    int iters = K >> 4;

    auto load_stage = [&](int s, int kt) {
#pragma unroll
        for (int p = 0; p < 2; p++) {
            int r = aRow + p * 64;
            uint32_t sa = (uint32_t)__cvta_generic_to_shared(&As[s][r][aCol]);
            cp_async16(sa, A + (size_t)(rowT + r) * K + kt + aCol);
        }
#pragma unroll
        for (int p = 0; p < 2; p++) {
            int r = bRow + p * 8;
            uint32_t sa = (uint32_t)__cvta_generic_to_shared(&Bs[s][r][bCol]);
            cp_async16(sa, B + (size_t)(kt + r) * Nc + colT + bCol);
        }
    };

    load_stage(0, 0);
    cp_commit();

    for (int it = 0; it < iters; it++) {
        int cur = it & 1;
        bool has_next = (it + 1 < iters);
        if (has_next) {
            load_stage((it + 1) & 1, (it + 1) << 4);
            cp_commit();
            asm volatile("cp.async.wait_group 1;");
        } else {
            asm volatile("cp.async.wait_group 0;");
        }
        __syncthreads();

#pragma unroll
        for (int kk = 0; kk < 16; kk += 8) {
            float af[2][4];
#pragma unroll
            for (int i = 0; i < 2; i++) {
                int m0 = wm + i * 16 + gr;
                af[i][0] = As[cur][m0][kk + tg];
                af[i][1] = As[cur][m0 + 8][kk + tg];
                af[i][2] = As[cur][m0][kk + tg + 4];
                af[i][3] = As[cur][m0 + 8][kk + tg + 4];
            }
            float bf[8][2];
#pragma unroll
            for (int j = 0; j < 8; j++) {
                int n0 = wn + j * 8 + gr;
                bf[j][0] = Bs[cur][kk + tg][n0];
                bf[j][1] = Bs[cur][kk + tg + 4][n0];
            }
#pragma unroll
            for (int i = 0; i < 2; i++)
#pragma unroll
                for (int j = 0; j < 8; j++) {
                    asm volatile(
                        "mma.sync.aligned.m16n8k8.row.col.f32.tf32.tf32.f32 "
                        "{%0,%1,%2,%3},{%4,%5,%6,%7},{%8,%9},{%0,%1,%2,%3};"
                        : "+f"(acc[i][j][0]), "+f"(acc[i][j][1]),
                          "+f"(acc[i][j][2]), "+f"(acc[i][j][3])
                        : "r"(__float_as_uint(af[i][0])), "r"(__float_as_uint(af[i][1])),
                          "r"(__float_as_uint(af[i][2])), "r"(__float_as_uint(af[i][3])),
                          "r"(__float_as_uint(bf[j][0])), "r"(__float_as_uint(bf[j][1])));
                }
        }
        __syncthreads();
    }

#pragma unroll
    for (int i = 0; i < 2; i++) {
        int r0 = rowT + wm + i * 16 + gr;
#pragma unroll
        for (int j = 0; j < 8; j++) {
            int ccol = colT + wn + j * 8 + tg * 2;
            *reinterpret_cast<float2*>(C + (size_t)r0 * Nc + ccol) =
                make_float2(acc[i][j][0], acc[i][j][1]);
            *reinterpret_cast<float2*>(C + (size_t)(r0 + 8) * Nc + ccol) =
                make_float2(acc[i][j][2], acc[i][j][3]);
        }
    }
}

// ---------------- attention projections el/er (+ zero s1/s2, FULL range) ----------------
__global__ void k_attn(const float* __restrict__ al, const float* __restrict__ ar, int d) {
    if (blockIdx.x == 0) {   // zero ALL MAXD stats entries: 256 threads x 2 each
        g_s1[threadIdx.x] = 0.f;
        g_s1[threadIdx.x + 256] = 0.f;
        g_s2[threadIdx.x] = 0.f;
        g_s2[threadIdx.x + 256] = 0.f;
    }
    int gw = (blockIdx.x * blockDim.x + threadIdx.x) >> 5;
    int lane = threadIdx.x & 31;
    if (gw >= NN * HH) return;
    int n = gw >> 1, hd = gw & 1;
    const float4* hr = (const float4*)(g_h + (size_t)n * (2 * d) + hd * d);
    const float4* av = (const float4*)(al + hd * d);
    const float4* bv = (const float4*)(ar + hd * d);
    int q = d >> 2;
    float sl = 0.f, sr = 0.f;
    for (int c = lane; c < q; c += 32) {
        float4 v = hr[c], a = av[c], b = bv[c];
        sl += v.x * a.x + v.y * a.y + v.z * a.z + v.w * a.w;
        sr += v.x * b.x + v.y * b.y + v.z * b.z + v.w * b.w;
    }
#pragma unroll
    for (int o = 16; o > 0; o >>= 1) {
        sl += __shfl_down_sync(0xffffffffu, sl, o);
        sr += __shfl_down_sync(0xffffffffu, sr, o);
    }
    if (lane == 0) { g_el[gw] = sl; g_er[gw] = sr; }
}

// ---------------- per-dst softmax + weighted aggregation (+ residual) ----------------
__global__ void __launch_bounds__(256) k_agg(int d) {
    const int HD = 2 * d;
    int n = blockIdx.x;
    int tid = threadIdx.x;
    int start = g_indptr[n];
    int deg = g_indptr[n + 1] - start;
    __shared__ float s_m0, s_m1, s_i0, s_i1;
    __shared__ int s_src[32];
    __shared__ float s_w[32][2];
    float er0 = g_er[n * 2 + 0];
    float er1 = g_er[n * 2 + 1];

    if (tid < 32) {
        float m0 = -1e30f, m1 = -1e30f;
        for (int j = tid; j < deg; j += 32) {
            int s = g_esrc[start + j];
            float e0 = lrelu(g_el[s * 2 + 0] + er0, 0.2f);
            float e1 = lrelu(g_el[s * 2 + 1] + er1, 0.2f);
            m0 = fmaxf(m0, e0); m1 = fmaxf(m1, e1);
        }
#pragma unroll
        for (int o = 16; o > 0; o >>= 1) {
            m0 = fmaxf(m0, __shfl_xor_sync(0xffffffffu, m0, o));
            m1 = fmaxf(m1, __shfl_xor_sync(0xffffffffu, m1, o));
        }
        float z0 = 0.f, z1 = 0.f;
        for (int j = tid; j < deg; j += 32) {
            int s = g_esrc[start + j];
            float e0 = lrelu(g_el[s * 2 + 0] + er0, 0.2f);
            float e1 = lrelu(g_el[s * 2 + 1] + er1, 0.2f);
            z0 += expf(e0 - m0);
            z1 += expf(e1 - m1);
        }
#pragma unroll
        for (int o = 16; o > 0; o >>= 1) {
            z0 += __shfl_xor_sync(0xffffffffu, z0, o);
            z1 += __shfl_xor_sync(0xffffffffu, z1, o);
        }
        if (tid == 0) {
            s_m0 = m0; s_m1 = m1;
            s_i0 = (deg > 0) ? 1.f / z0 : 0.f;
            s_i1 = (deg > 0) ? 1.f / z1 : 0.f;
        }
    }
    __syncthreads();
    float m0 = s_m0, m1 = s_m1, i0 = s_i0, i1 = s_i1;

    float acc[4] = {0.f, 0.f, 0.f, 0.f};
    for (int c0 = 0; c0 < deg; c0 += 32) {
        int cn = min(32, deg - c0);
        if (tid < cn) {
            int s = g_esrc[start + c0 + tid];
            s_src[tid] = s;
            float e0 = lrelu(g_el[s * 2 + 0] + er0, 0.2f);
            float e1 = lrelu(g_el[s * 2 + 1] + er1, 0.2f);
            s_w[tid][0] = expf(e0 - m0) * i0;
            s_w[tid][1] = expf(e1 - m1) * i1;
        }
        __syncthreads();
        int j = 0;
        for (; j + 1 < cn; j += 2) {
            const float* h0 = g_h + (size_t)s_src[j] * HD;
            const float* h1 = g_h + (size_t)s_src[j + 1] * HD;
            float wa0 = s_w[j][0], wa1 = s_w[j][1];
            float wb0 = s_w[j + 1][0], wb1 = s_w[j + 1][1];
#pragma unroll
            for (int k = 0; k < 4; k++) {
                int c = tid + k * 256;
                if (c < HD) {
                    float wa = (c < d) ? wa0 : wa1;
                    float wb = (c < d) ? wb0 : wb1;
                    float v0 = __ldg(h0 + c);
                    float v1 = __ldg(h1 + c);
                    acc[k] = fmaf(wa, v0, acc[k]);
                    acc[k] = fmaf(wb, v1, acc[k]);
                }
            }
        }
        if (j < cn) {
            const float* h0 = g_h + (size_t)s_src[j] * HD;
            float wa0 = s_w[j][0], wa1 = s_w[j][1];
#pragma unroll
            for (int k = 0; k < 4; k++) {
                int c = tid + k * 256;
                if (c < HD) {
                    float wa = (c < d) ? wa0 : wa1;
                    acc[k] = fmaf(wa, __ldg(h0 + c), acc[k]);
                }
            }
        }
        __syncthreads();
    }
#pragma unroll
    for (int k = 0; k < 4; k++) {
        int c = tid + k * 256;
        if (c < HD) g_x[(size_t)n * HD + c] = acc[k] + g_r[(size_t)n * HD + c];
    }
}

// ---------------- GraphNorm stats ----------------
__global__ void k_colstats(int d) {
    int r0 = blockIdx.x * 128;
    int c0 = threadIdx.x, c1 = threadIdx.x + 256;
    float a0 = 0.f, b0 = 0.f, a1 = 0.f, b1 = 0.f;
    for (int r = 0; r < 128; r++) {
        const float* row = g_x + (size_t)(r0 + r) * d;
        if (c0 < d) { float v = row[c0]; a0 += v; b0 += v * v; }
        if (c1 < d) { float v = row[c1]; a1 += v; b1 += v * v; }
    }
    if (c0 < d) { atomicAdd(&g_s1[c0], a0); atomicAdd(&g_s2[c0], b0); }
    if (c1 < d) { atomicAdd(&g_s1[c1], a1); atomicAdd(&g_s2[c1], b1); }
}

__global__ void k_finstats(const float* __restrict__ gamma, const float* __restrict__ beta,
                           const float* __restrict__ alpha, int d) {
    int c = blockIdx.x * blockDim.x + threadIdx.x;
    if (c >= d) return;
    const float inv_nh = 1.f / (float)(NN * HH);
    float mean = g_s1[c] * inv_nh;
    float ex2 = g_s2[c] * inv_nh;
    float a = alpha[c];
    float var = ex2 - 2.f * a * mean * mean + a * a * mean * mean;
    float inv = rsqrtf(var + 1e-5f);
    float sc = gamma[c] * inv;
    g_scale[c] = sc;
    g_bias[c] = beta[c] - sc * a * mean;
}

// ---------------- normalize + lrelu + head-mean partials ----------------
__global__ void k_norm(const int* __restrict__ gid, int d, int off) {
    int nb = blockIdx.x * 64;
    int g = gid[nb];
    int c0 = threadIdx.x, c1 = threadIdx.x + 256;
    float acc0 = 0.f, acc1 = 0.f;
    float sc0 = 0.f, bi0 = 0.f, sc1 = 0.f, bi1 = 0.f;
    if (c0 < d) { sc0 = g_scale[c0]; bi0 = g_bias[c0]; }
    if (c1 < d) { sc1 = g_scale[c1]; bi1 = g_bias[c1]; }
    for (int i = 0; i < 64; i++) {
        size_t base = (size_t)(nb + i) * 2 * d;
        if (c0 < d) {
            float y0 = lrelu(g_x[base + c0] * sc0 + bi0, 0.01f);
            float y1 = lrelu(g_x[base + d + c0] * sc0 + bi0, 0.01f);
            g_y[base + c0] = y0;
            g_y[base + d + c0] = y1;
            acc0 += y0 + y1;
        }
        if (c1 < d) {
            float y0 = lrelu(g_x[base + c1] * sc1 + bi1, 0.01f);
            float y1 = lrelu(g_x[base + d + c1] * sc1 + bi1, 0.01f);
            g_y[base + c1] = y0;
            g_y[base + d + c1] = y1;
            acc1 += y0 + y1;
        }
    }
    if (c0 < d) atomicAdd(&g_parts[g * OUTC + off + c0], acc0);
    if (c1 < d) atomicAdd(&g_parts[g * OUTC + off + c1], acc1);
}

// ---------------- final ----------------
__global__ void k_final(float* __restrict__ out) {
    int i = blockIdx.x * blockDim.x + threadIdx.x;
    if (i < BB * OUTC) {
        int b = i / OUTC;
        float v = g_parts[i] / (2.f * (float)g_counts[b]);
        out[i] = lrelu(v, 0.01f);
    }
}

// ---------------- launch ----------------
extern "C" void kernel_launch(void* const* d_in, const int* in_sizes, int n_in,
                              void* d_out, int out_size) {
    const float* nf = (const float*)d_in[0];
    const float* W[3]  = {(const float*)d_in[1],  (const float*)d_in[8],  (const float*)d_in[15]};
    const float* AL[3] = {(const float*)d_in[2],  (const float*)d_in[9],  (const float*)d_in[16]};
    const float* AR[3] = {(const float*)d_in[3],  (const float*)d_in[10], (const float*)d_in[17]};
    const float* RW[3] = {(const float*)d_in[4],  (const float*)d_in[11], (const float*)d_in[18]};
    const float* GA[3] = {(const float*)d_in[5],  (const float*)d_in[12], (const float*)d_in[19]};
    const float* BE[3] = {(const float*)d_in[6],  (const float*)d_in[13], (const float*)d_in[20]};
    const float* AP[3] = {(const float*)d_in[7],  (const float*)d_in[14], (const float*)d_in[21]};
    const int* src = (const int*)d_in[22];
    const int* dst = (const int*)d_in[23];
    const int* gid = (const int*)d_in[24];
    float* out = (float*)d_out;

    k_zero<<<(NN + 255) / 256, 256>>>();
    k_build<<<EE / 256, 256>>>(dst, gid);
    k_scan1<<<64, 256>>>();
    k_scan2<<<1, 64>>>();
    k_scan3<<<NN / 256, 256>>>();
    k_scatter<<<EE / 256, 256>>>(src, dst);

    const int dims[3] = {128, 256, 512};
    const int offs[3] = {0, 128, 384};
    for (int l = 0; l < 3; l++) {
        int d = dims[l], in = d, HD = 2 * d;
        int use_ext = (l == 0) ? 1 : 0;
        dim3 gg(HD / 128, NN / 128, 2);
        k_mma<<<gg, 256>>>(nf, use_ext, W[l], RW[l], in, HD);
        k_attn<<<(NN * HH * 32) / 256, 256>>>(AL[l], AR[l], d);
        k_agg<<<NN, 256>>>(d);
        k_colstats<<<(NN * HH) / 128, 256>>>(d);
        k_finstats<<<(d + 255) / 256, 256>>>(GA[l], BE[l], AP[l], d);
        k_norm<<<NN / 64, 256>>>(gid, d, offs[l]);
    }
    k_final<<<(BB * OUTC + 255) / 256, 256>>>(out);
}

// round 9
// speedup vs baseline: 2.0425x; 1.0096x over previous
#include <cuda_runtime.h>
#include <math.h>
#include <stdint.h>

#define NN 16384
#define EE 131072
#define BB 16
#define HH 2
#define MAXD 512
#define MAXHD 1024
#define OUTC 896

// k_mma dynamic smem layout (floats):
//   As: 3 stages of [128][20]  -> 3*2560
//   Bs: 3 stages of [16][136]  -> 3*2176
#define AS_STAGE 2560
#define BS_STAGE 2176
#define SMEM_FLOATS (3 * (AS_STAGE + BS_STAGE))
#define SMEM_BYTES (SMEM_FLOATS * 4)

// ---------------- scratch (device globals; no allocation) ----------------
__device__ float g_x[(size_t)NN * MAXHD];
__device__ float g_y[(size_t)NN * MAXHD];
__device__ float g_h[(size_t)NN * MAXHD];
__device__ float g_r[(size_t)NN * MAXHD];
__device__ float g_el[NN * HH];
__device__ float g_er[NN * HH];
__device__ int   g_indptr[NN + 1];
__device__ int   g_cnt[NN];
__device__ int   g_cur[NN];
__device__ int   g_esrc[EE];
__device__ int   g_bsum[64];
__device__ int   g_boff[64];
__device__ float g_s1[MAXD];
__device__ float g_s2[MAXD];
__device__ float g_scale[MAXD];
__device__ float g_bias[MAXD];
__device__ float g_parts[BB * OUTC];
__device__ int   g_counts[BB];

__device__ __forceinline__ float lrelu(float v, float s) { return v > 0.f ? v : s * v; }

__device__ __forceinline__ void cp_async16(uint32_t saddr, const void* gptr) {
    asm volatile("cp.async.cg.shared.global [%0], [%1], 16;" :: "r"(saddr), "l"(gptr));
}
__device__ __forceinline__ void cp_commit() { asm volatile("cp.async.commit_group;"); }

// ---------------- front: zero + hist/counts + parallel scan ----------------
__global__ void k_zero() {
    int i = blockIdx.x * blockDim.x + threadIdx.x;
    if (i < BB * OUTC) g_parts[i] = 0.f;
    if (i < BB) g_counts[i] = 0;
    if (i < NN) g_cnt[i] = 0;
}

__global__ void k_build(const int* __restrict__ dst, const int* __restrict__ gid) {
    int i = blockIdx.x * blockDim.x + threadIdx.x;
    if (i < EE) atomicAdd(&g_cnt[dst[i]], 1);
    if (i < NN) atomicAdd(&g_counts[gid[i]], 1);
}

__global__ void k_scan1() {  // 64 blocks x 256
    __shared__ int sm[256];
    int tid = threadIdx.x;
    int i = blockIdx.x * 256 + tid;
    int v = g_cnt[i];
    sm[tid] = v;
    __syncthreads();
    for (int off = 1; off < 256; off <<= 1) {
        int t = (tid >= off) ? sm[tid - off] : 0;
        __syncthreads();
        sm[tid] += t;
        __syncthreads();
    }
    g_indptr[i] = sm[tid] - v;
    g_cur[i] = 0;
    if (tid == 255) g_bsum[blockIdx.x] = sm[255];
}

__global__ void k_scan2() {  // 1 block x 64
    __shared__ int sm[64];
    int tid = threadIdx.x;
    int v = g_bsum[tid];
    sm[tid] = v;
    __syncthreads();
    for (int off = 1; off < 64; off <<= 1) {
        int t = (tid >= off) ? sm[tid - off] : 0;
        __syncthreads();
        sm[tid] += t;
        __syncthreads();
    }
    g_boff[tid] = sm[tid] - v;
    if (tid == 63) g_indptr[NN] = sm[63];
}

__global__ void k_scan3() {
    int i = blockIdx.x * blockDim.x + threadIdx.x;
    if (i < NN) g_indptr[i] += g_boff[i >> 8];
}

__global__ void k_scatter(const int* __restrict__ src, const int* __restrict__ dst) {
    int i = blockIdx.x * blockDim.x + threadIdx.x;
    if (i < EE) {
        int d = dst[i];
        int p = g_indptr[d] + atomicAdd(&g_cur[d], 1);
        g_esrc[p] = src[i];
    }
}

// ---------------- TF32 tensor-core GEMM, cp.async 3-stage pipelined ----------------
// C[M,Nc] = A[M,K] @ B[K,Nc]. Block 128x128, BK=16, 3 stages (dynamic smem).
// blockIdx.z: 0 -> B=W, C=g_h; 1 -> B=rW, C=g_r.
__global__ void __launch_bounds__(256) k_mma(const float* __restrict__ Aext, int use_ext,
                                             const float* __restrict__ Bw,
                                             const float* __restrict__ Br,
                                             int K, int Nc) {
    extern __shared__ float smem[];
    float* AsBase = smem;                    // 3 * [128][20]
    float* BsBase = smem + 3 * AS_STAGE;     // 3 * [16][136]

    const float* A = use_ext ? Aext : g_y;
    const float* B = blockIdx.z ? Br : Bw;
    float* C = blockIdx.z ? g_r : g_h;

    int tid = threadIdx.x;
    int lane = tid & 31;
    int warp = tid >> 5;
    int wm = (warp >> 1) * 32;
    int wn = (warp & 1) * 64;
    int rowT = blockIdx.y * 128;
    int colT = blockIdx.x * 128;
    int gr = lane >> 2;
    int tg = lane & 3;

    int aRow = tid >> 2;            // 0..63
    int aCol = (tid & 3) * 4;       // 0,4,8,12
    int bRow = tid >> 5;            // 0..7
    int bCol = (tid & 31) * 4;      // 0..124

    float acc[2][8][4];
#pragma unroll
    for (int i = 0; i < 2; i++)
#pragma unroll
        for (int j = 0; j < 8; j++)
#pragma unroll
            for (int c = 0; c < 4; c++) acc[i][j][c] = 0.f;

    int iters = K >> 4;   // >= 8 always

    auto load_stage = [&](int s, int kt) {
        float* As = AsBase + s * AS_STAGE;
        float* Bs = BsBase + s * BS_STAGE;
#pragma unroll
        for (int p = 0; p < 2; p++) {
            int r = aRow + p * 64;
            uint32_t sa = (uint32_t)__cvta_generic_to_shared(&As[r * 20 + aCol]);
            cp_async16(sa, A + (size_t)(rowT + r) * K + kt + aCol);
        }
#pragma unroll
        for (int p = 0; p < 2; p++) {
            int r = bRow + p * 8;
            uint32_t sa = (uint32_t)__cvta_generic_to_shared(&Bs[r * 136 + bCol]);
            cp_async16(sa, B + (size_t)(kt + r) * Nc + colT + bCol);
        }
    };

    load_stage(0, 0);
    cp_commit();
    load_stage(1, 16);
    cp_commit();

    for (int it = 0; it < iters; it++) {
        if (it + 1 < iters) asm volatile("cp.async.wait_group 1;");
        else                asm volatile("cp.async.wait_group 0;");
        __syncthreads();

        if (it + 2 < iters) {
            load_stage((it + 2) % 3, (it + 2) << 4);
            cp_commit();
        }

        int cur = it % 3;
        const float* As = AsBase + cur * AS_STAGE;
        const float* Bs = BsBase + cur * BS_STAGE;
#pragma unroll
        for (int kk = 0; kk < 16; kk += 8) {
            float af[2][4];
#pragma unroll
            for (int i = 0; i < 2; i++) {
                int m0 = wm + i * 16 + gr;
                af[i][0] = As[m0 * 20 + kk + tg];
                af[i][1] = As[(m0 + 8) * 20 + kk + tg];
                af[i][2] = As[m0 * 20 + kk + tg + 4];
                af[i][3] = As[(m0 + 8) * 20 + kk + tg + 4];
            }
            float bf[8][2];
#pragma unroll
            for (int j = 0; j < 8; j++) {
                int n0 = wn + j * 8 + gr;
                bf[j][0] = Bs[(kk + tg) * 136 + n0];
                bf[j][1] = Bs[(kk + tg + 4) * 136 + n0];
            }
#pragma unroll
            for (int i = 0; i < 2; i++)
#pragma unroll
                for (int j = 0; j < 8; j++) {
                    asm volatile(
                        "mma.sync.aligned.m16n8k8.row.col.f32.tf32.tf32.f32 "
                        "{%0,%1,%2,%3},{%4,%5,%6,%7},{%8,%9},{%0,%1,%2,%3};"
                        : "+f"(acc[i][j][0]), "+f"(acc[i][j][1]),
                          "+f"(acc[i][j][2]), "+f"(acc[i][j][3])
                        : "r"(__float_as_uint(af[i][0])), "r"(__float_as_uint(af[i][1])),
                          "r"(__float_as_uint(af[i][2])), "r"(__float_as_uint(af[i][3])),
                          "r"(__float_as_uint(bf[j][0])), "r"(__float_as_uint(bf[j][1])));
                }
        }
        __syncthreads();
    }

#pragma unroll
    for (int i = 0; i < 2; i++) {
        int r0 = rowT + wm + i * 16 + gr;
#pragma unroll
        for (int j = 0; j < 8; j++) {
            int ccol = colT + wn + j * 8 + tg * 2;
            *reinterpret_cast<float2*>(C + (size_t)r0 * Nc + ccol) =
                make_float2(acc[i][j][0], acc[i][j][1]);
            *reinterpret_cast<float2*>(C + (size_t)(r0 + 8) * Nc + ccol) =
                make_float2(acc[i][j][2], acc[i][j][3]);
        }
    }
}

// ---------------- attention projections el/er (+ zero s1/s2, FULL range) ----------------
__global__ void k_attn(const float* __restrict__ al, const float* __restrict__ ar, int d) {
    if (blockIdx.x == 0) {
        g_s1[threadIdx.x] = 0.f;
        g_s1[threadIdx.x + 256] = 0.f;
        g_s2[threadIdx.x] = 0.f;
        g_s2[threadIdx.x + 256] = 0.f;
    }
    int gw = (blockIdx.x * blockDim.x + threadIdx.x) >> 5;
    int lane = threadIdx.x & 31;
    if (gw >= NN * HH) return;
    int n = gw >> 1, hd = gw & 1;
    const float4* hr = (const float4*)(g_h + (size_t)n * (2 * d) + hd * d);
    const float4* av = (const float4*)(al + hd * d);
    const float4* bv = (const float4*)(ar + hd * d);
    int q = d >> 2;
    float sl = 0.f, sr = 0.f;
    for (int c = lane; c < q; c += 32) {
        float4 v = hr[c], a = av[c], b = bv[c];
        sl += v.x * a.x + v.y * a.y + v.z * a.z + v.w * a.w;
        sr += v.x * b.x + v.y * b.y + v.z * b.z + v.w * b.w;
    }
#pragma unroll
    for (int o = 16; o > 0; o >>= 1) {
        sl += __shfl_down_sync(0xffffffffu, sl, o);
        sr += __shfl_down_sync(0xffffffffu, sr, o);
    }
    if (lane == 0) { g_el[gw] = sl; g_er[gw] = sr; }
}

// ---------------- per-dst softmax + weighted aggregation (+ residual) ----------------
__global__ void __launch_bounds__(256) k_agg(int d) {
    const int HD = 2 * d;
    int n = blockIdx.x;
    int tid = threadIdx.x;
    int start = g_indptr[n];
    int deg = g_indptr[n + 1] - start;
    __shared__ float s_m0, s_m1, s_i0, s_i1;
    __shared__ int s_src[32];
    __shared__ float s_w[32][2];
    float er0 = g_er[n * 2 + 0];
    float er1 = g_er[n * 2 + 1];

    if (tid < 32) {
        float m0 = -1e30f, m1 = -1e30f;
        for (int j = tid; j < deg; j += 32) {
            int s = g_esrc[start + j];
            float e0 = lrelu(g_el[s * 2 + 0] + er0, 0.2f);
            float e1 = lrelu(g_el[s * 2 + 1] + er1, 0.2f);
            m0 = fmaxf(m0, e0); m1 = fmaxf(m1, e1);
        }
#pragma unroll
        for (int o = 16; o > 0; o >>= 1) {
            m0 = fmaxf(m0, __shfl_xor_sync(0xffffffffu, m0, o));
            m1 = fmaxf(m1, __shfl_xor_sync(0xffffffffu, m1, o));
        }
        float z0 = 0.f, z1 = 0.f;
        for (int j = tid; j < deg; j += 32) {
            int s = g_esrc[start + j];
            float e0 = lrelu(g_el[s * 2 + 0] + er0, 0.2f);
            float e1 = lrelu(g_el[s * 2 + 1] + er1, 0.2f);
            z0 += expf(e0 - m0);
            z1 += expf(e1 - m1);
        }
#pragma unroll
        for (int o = 16; o > 0; o >>= 1) {
            z0 += __shfl_xor_sync(0xffffffffu, z0, o);
            z1 += __shfl_xor_sync(0xffffffffu, z1, o);
        }
        if (tid == 0) {
            s_m0 = m0; s_m1 = m1;
            s_i0 = (deg > 0) ? 1.f / z0 : 0.f;
            s_i1 = (deg > 0) ? 1.f / z1 : 0.f;
        }
    }
    __syncthreads();
    float m0 = s_m0, m1 = s_m1, i0 = s_i0, i1 = s_i1;

    float acc[4] = {0.f, 0.f, 0.f, 0.f};
    for (int c0 = 0; c0 < deg; c0 += 32) {
        int cn = min(32, deg - c0);
        if (tid < cn) {
            int s = g_esrc[start + c0 + tid];
            s_src[tid] = s;
            float e0 = lrelu(g_el[s * 2 + 0] + er0, 0.2f);
            float e1 = lrelu(g_el[s * 2 + 1] + er1, 0.2f);
            s_w[tid][0] = expf(e0 - m0) * i0;
            s_w[tid][1] = expf(e1 - m1) * i1;
        }
        __syncthreads();
        int j = 0;
        for (; j + 1 < cn; j += 2) {
            const float* h0 = g_h + (size_t)s_src[j] * HD;
            const float* h1 = g_h + (size_t)s_src[j + 1] * HD;
            float wa0 = s_w[j][0], wa1 = s_w[j][1];
            float wb0 = s_w[j + 1][0], wb1 = s_w[j + 1][1];
#pragma unroll
            for (int k = 0; k < 4; k++) {
                int c = tid + k * 256;
                if (c < HD) {
                    float wa = (c < d) ? wa0 : wa1;
                    float wb = (c < d) ? wb0 : wb1;
                    float v0 = __ldg(h0 + c);
                    float v1 = __ldg(h1 + c);
                    acc[k] = fmaf(wa, v0, acc[k]);
                    acc[k] = fmaf(wb, v1, acc[k]);
                }
            }
        }
        if (j < cn) {
            const float* h0 = g_h + (size_t)s_src[j] * HD;
            float wa0 = s_w[j][0], wa1 = s_w[j][1];
#pragma unroll
            for (int k = 0; k < 4; k++) {
                int c = tid + k * 256;
                if (c < HD) {
                    float wa = (c < d) ? wa0 : wa1;
                    acc[k] = fmaf(wa, __ldg(h0 + c), acc[k]);
                }
            }
        }
        __syncthreads();
    }
#pragma unroll
    for (int k = 0; k < 4; k++) {
        int c = tid + k * 256;
        if (c < HD) g_x[(size_t)n * HD + c] = acc[k] + g_r[(size_t)n * HD + c];
    }
}

// ---------------- GraphNorm stats ----------------
__global__ void k_colstats(int d) {
    int r0 = blockIdx.x * 128;
    int c4 = threadIdx.x;
    int q = d >> 2;
    if (c4 >= q) return;
    float a0 = 0.f, a1 = 0.f, a2 = 0.f, a3 = 0.f;
    float b0 = 0.f, b1 = 0.f, b2 = 0.f, b3 = 0.f;
    for (int r = 0; r < 128; r++) {
        const float4* row = (const float4*)(g_x + (size_t)(r0 + r) * d);
        float4 v = row[c4];
        a0 += v.x; b0 += v.x * v.x;
        a1 += v.y; b1 += v.y * v.y;
        a2 += v.z; b2 += v.z * v.z;
        a3 += v.w; b3 += v.w * v.w;
    }
    int c = c4 * 4;
    atomicAdd(&g_s1[c + 0], a0); atomicAdd(&g_s2[c + 0], b0);
    atomicAdd(&g_s1[c + 1], a1); atomicAdd(&g_s2[c + 1], b1);
    atomicAdd(&g_s1[c + 2], a2); atomicAdd(&g_s2[c + 2], b2);
    atomicAdd(&g_s1[c + 3], a3); atomicAdd(&g_s2[c + 3], b3);
}

__global__ void k_finstats(const float* __restrict__ gamma, const float* __restrict__ beta,
                           const float* __restrict__ alpha, int d) {
    int c = blockIdx.x * blockDim.x + threadIdx.x;
    if (c >= d) return;
    const float inv_nh = 1.f / (float)(NN * HH);
    float mean = g_s1[c] * inv_nh;
    float ex2 = g_s2[c] * inv_nh;
    float a = alpha[c];
    float var = ex2 - 2.f * a * mean * mean + a * a * mean * mean;
    float inv = rsqrtf(var + 1e-5f);
    float sc = gamma[c] * inv;
    g_scale[c] = sc;
    g_bias[c] = beta[c] - sc * a * mean;
}

// ---------------- normalize + lrelu + head-mean partials ----------------
__global__ void k_norm(const int* __restrict__ gid, int d, int off, int writeY) {
    int nb = blockIdx.x * 64;
    int g = gid[nb];
    int c0 = threadIdx.x, c1 = threadIdx.x + 256;
    float acc0 = 0.f, acc1 = 0.f;
    float sc0 = 0.f, bi0 = 0.f, sc1 = 0.f, bi1 = 0.f;
    if (c0 < d) { sc0 = g_scale[c0]; bi0 = g_bias[c0]; }
    if (c1 < d) { sc1 = g_scale[c1]; bi1 = g_bias[c1]; }
    for (int i = 0; i < 64; i++) {
        size_t base = (size_t)(nb + i) * 2 * d;
        if (c0 < d) {
            float y0 = lrelu(g_x[base + c0] * sc0 + bi0, 0.01f);
            float y1 = lrelu(g_x[base + d + c0] * sc0 + bi0, 0.01f);
            if (writeY) {
                g_y[base + c0] = y0;
                g_y[base + d + c0] = y1;
            }
            acc0 += y0 + y1;
        }
        if (c1 < d) {
            float y0 = lrelu(g_x[base + c1] * sc1 + bi1, 0.01f);
            float y1 = lrelu(g_x[base + d + c1] * sc1 + bi1, 0.01f);
            if (writeY) {
                g_y[base + c1] = y0;
                g_y[base + d + c1] = y1;
            }
            acc1 += y0 + y1;
        }
    }
    if (c0 < d) atomicAdd(&g_parts[g * OUTC + off + c0], acc0);
    if (c1 < d) atomicAdd(&g_parts[g * OUTC + off + c1], acc1);
}

// ---------------- final ----------------
__global__ void k_final(float* __restrict__ out) {
    int i = blockIdx.x * blockDim.x + threadIdx.x;
    if (i < BB * OUTC) {
        int b = i / OUTC;
        float v = g_parts[i] / (2.f * (float)g_counts[b]);
        out[i] = lrelu(v, 0.01f);
    }
}

// ---------------- launch ----------------
extern "C" void kernel_launch(void* const* d_in, const int* in_sizes, int n_in,
                              void* d_out, int out_size) {
    const float* nf = (const float*)d_in[0];
    const float* W[3]  = {(const float*)d_in[1],  (const float*)d_in[8],  (const float*)d_in[15]};
    const float* AL[3] = {(const float*)d_in[2],  (const float*)d_in[9],  (const float*)d_in[16]};
    const float* AR[3] = {(const float*)d_in[3],  (const float*)d_in[10], (const float*)d_in[17]};
    const float* RW[3] = {(const float*)d_in[4],  (const float*)d_in[11], (const float*)d_in[18]};
    const float* GA[3] = {(const float*)d_in[5],  (const float*)d_in[12], (const float*)d_in[19]};
    const float* BE[3] = {(const float*)d_in[6],  (const float*)d_in[13], (const float*)d_in[20]};
    const float* AP[3] = {(const float*)d_in[7],  (const float*)d_in[14], (const float*)d_in[21]};
    const int* src = (const int*)d_in[22];
    const int* dst = (const int*)d_in[23];
    const int* gid = (const int*)d_in[24];
    float* out = (float*)d_out;

    cudaFuncSetAttribute(k_mma, cudaFuncAttributeMaxDynamicSharedMemorySize, SMEM_BYTES);

    const int dims[3] = {128, 256, 512};
    const int offs[3] = {0, 128, 384};

    // front (5 launches) so layer-0 k_mma is launch index 5 -> captured by ncu -s 5 -c 1
    k_zero<<<(NN + 255) / 256, 256>>>();
    k_build<<<EE / 256, 256>>>(dst, gid);
    k_scan1<<<64, 256>>>();
    k_scan2<<<1, 64>>>();
    k_scan3<<<NN / 256, 256>>>();

    // layer 0 GEMM (independent of CSR) -- profiled launch
    {
        dim3 gg(dims[0] * 2 / 128, NN / 128, 2);
        k_mma<<<gg, 256, SMEM_BYTES>>>(nf, 1, W[0], RW[0], dims[0], dims[0] * 2);
    }
    k_scatter<<<EE / 256, 256>>>(src, dst);

    for (int l = 0; l < 3; l++) {
        int d = dims[l], in = d, HD = 2 * d;
        if (l > 0) {
            dim3 gg(HD / 128, NN / 128, 2);
            k_mma<<<gg, 256, SMEM_BYTES>>>(nf, 0, W[l], RW[l], in, HD);
        }
        k_attn<<<(NN * HH * 32) / 256, 256>>>(AL[l], AR[l], d);
        k_agg<<<NN, 256>>>(d);
        k_colstats<<<(NN * HH) / 128, 256>>>(d);
        k_finstats<<<(d + 255) / 256, 256>>>(GA[l], BE[l], AP[l], d);
        k_norm<<<NN / 64, 256>>>(gid, d, offs[l], (l < 2) ? 1 : 0);
    }
    k_final<<<(BB * OUTC + 255) / 256, 256>>>(out);
}